// round 6
// baseline (speedup 1.0000x reference)
#include <cuda_runtime.h>
#include <math.h>

// ---- problem constants ----
#define A_DIM 56
#define E_DIM 128
#define LAMBDA_INIT 0.7f
#define LN_EPS 1e-5f
#define SCALING 0.25f   // HD^-0.5, HD=16

// ---- repacked weight sizes (32-bit words) ----
#define W1_WORDS (2 * 49 * 256)    // conv1: 2 m-groups, K=392 (49 ksteps)
#define W2_WORDS (4 * 112 * 256)   // conv2: 4 m-groups, K=896 (112 ksteps)
#define W3_WORDS (4 * 16 * 256)    // kproj: 4 m-groups, K=128 (16 ksteps)
#define W_TOTAL  (W1_WORDS + W2_WORDS + W3_WORDS)

__device__ __align__(16) unsigned g_w1[W1_WORDS];
__device__ __align__(16) unsigned g_w2[W2_WORDS];
__device__ __align__(16) unsigned g_w3[W3_WORDS];

// ---- smem layout (32-bit words), ONE batch per CTA ----
#define SX_STRIDE  136             // ≡ 8 (mod 32) -> conflict-free B loads
#define SZ_SX      (64 * SX_STRIDE)        // 8704
#define SH1_STRIDE 72              // ≡ 8 (mod 32)
#define SZ_SH1     (128 * SH1_STRIDE)      // 9216 ; reused as SK fp32 [64][132]
#define SK_STRIDE  132

#define OFF_SX   0
#define OFF_SH1  (OFF_SX + SZ_SX)          // 8704
#define OFF_SQ   (OFF_SH1 + SZ_SH1)        // 17920  [2][128] per-nh partial sums
#define OFF_SQN  (OFF_SQ + 256)            // [128]
#define OFF_SA   (OFF_SQN + 128)           // [8][60]
#define OFF_SA2  (OFF_SA + 480)            // [4][60]
#define OFF_SC   (OFF_SA2 + 240)
#define SMEM_WORDS (OFF_SC + 4)            // 19028 words = 76112 B -> 2 CTAs/SM

__device__ __forceinline__ unsigned f2tf(float f) {
    unsigned u;
    asm("cvt.rna.tf32.f32 %0, %1;" : "=r"(u) : "f"(f));
    return u;
}
__device__ __forceinline__ float silu_f(float v) {
    return v / (1.0f + __expf(-v));
}
__device__ __forceinline__ void mma_tf32(float* d, const unsigned* a, const unsigned* b) {
    asm volatile(
        "mma.sync.aligned.m16n8k8.row.col.f32.tf32.tf32.f32 "
        "{%0,%1,%2,%3}, {%4,%5,%6,%7}, {%8,%9}, {%0,%1,%2,%3};"
        : "+f"(d[0]), "+f"(d[1]), "+f"(d[2]), "+f"(d[3])
        : "r"(a[0]), "r"(a[1]), "r"(a[2]), "r"(a[3]), "r"(b[0]), "r"(b[1]));
}

// ================== weight repack: fragment-order tf32, TAP-MAJOR k ==================
// word idx per m-group block = ks*256 + j2*64 + lane*2 + p; j = 2*j2+p, mi = j>>2, r = j&3,
// row = mg*32 + mi*16 + g + (r&1)*8, k' = ks*8 + tg + (r>=2)*4.
// conv1: k' = dk*56 + ia -> src col = ia*7 + dk ; conv2: k' = dk*128 + ie -> col = ie*7 + dk
__global__ void __launch_bounds__(256)
repack_kernel(const float* __restrict__ w_emb,
              const float* __restrict__ w_atlas,
              const float* __restrict__ w_k)
{
    int i = blockIdx.x * 256 + threadIdx.x;
    if (i >= W_TOTAL) return;

    const float* src;
    unsigned* dst;
    int K, src_stride, row_lim, ii, which;
    if (i < W1_WORDS) {
        ii = i; src = w_emb; dst = g_w1; K = 49; src_stride = 392; row_lim = 56; which = 1;
    } else if (i < W1_WORDS + W2_WORDS) {
        ii = i - W1_WORDS; src = w_atlas; dst = g_w2; K = 112; src_stride = 896; row_lim = 128; which = 2;
    } else {
        ii = i - W1_WORDS - W2_WORDS; src = w_k; dst = g_w3; K = 16; src_stride = 128; row_lim = 128; which = 3;
    }
    int p    = ii & 1;
    int lane = (ii >> 1) & 31;
    int j2   = (ii >> 6) & 3;
    int blk  = ii >> 8;
    int ks   = blk % K;
    int mg   = blk / K;
    int j    = j2 * 2 + p;
    int mi   = j >> 2, r = j & 3;
    int g = lane >> 2, tg = lane & 3;
    int row = mg * 32 + mi * 16 + g + ((r & 1) ? 8 : 0);
    int kk  = ks * 8 + tg + ((r >= 2) ? 4 : 0);
    int col;
    if (which == 1)      col = (kk % 56) * 7 + kk / 56;
    else if (which == 2) col = (kk % 128) * 7 + kk / 128;
    else                 col = kk;
    float v = (row < row_lim) ? src[row * src_stride + col] : 0.f;
    dst[ii] = f2tf(v);
}

extern __shared__ unsigned smw[];

__global__ void __launch_bounds__(256, 2)
atlas_mdattn_tc(
    const float* __restrict__ x,       // [B,56,128]
    const float* __restrict__ b_emb,   // [56]
    const float* __restrict__ b_atlas, // [128]
    const float* __restrict__ qn_w, const float* __restrict__ qn_b,
    const float* __restrict__ kn_w, const float* __restrict__ kn_b,
    const float* __restrict__ lq1, const float* __restrict__ lk1,
    const float* __restrict__ lq2, const float* __restrict__ lk2,
    float* __restrict__ out)           // [B,56]
{
    const int t = threadIdx.x;
    const int lane = t & 31, wid = t >> 5;
    const int g = lane >> 2, tg = lane & 3;

    unsigned* SX  = smw + OFF_SX;
    unsigned* SH1 = smw + OFF_SH1;
    float* Sq  = (float*)(smw + OFF_SQ);   // [2][128]
    float* Sqn = (float*)(smw + OFF_SQN);  // [128]
    float* SA  = (float*)(smw + OFF_SA);   // [8][60]
    float* SA2 = (float*)(smw + OFF_SA2);  // [4][60]
    float* Ssc = (float*)(smw + OFF_SC);
    float* SK  = (float*)SH1;              // [64][132] after conv2 done

    // ---------------- init ----------------
    {
        uint4 z = make_uint4(0, 0, 0, 0);
        uint4* p = (uint4*)smw;
        for (int i = t; i < (SZ_SX + SZ_SH1) / 4; i += 256) p[i] = z;
    }
    if (t == 0) {
        float s1 = 0.f, s2 = 0.f;
        #pragma unroll
        for (int d = 0; d < 16; ++d) { s1 += lq1[d] * lk1[d]; s2 += lq2[d] * lk2[d]; }
        Ssc[0] = __expf(s1) - __expf(s2) + LAMBDA_INIT;
    }
    __syncthreads();

    // load x (one batch), tf32, halo-padded
    const float* xb = x + (size_t)blockIdx.x * (A_DIM * E_DIM);
    for (int i = t; i < A_DIM * E_DIM; i += 256) {
        int l = i >> 7, e = i & 127;
        SX[l * SX_STRIDE + 3 + e] = f2tf(xb[i]);
    }
    __syncthreads();

    // ============ conv1: D[oa 64, e 128] = Wemb x im2col(x), K=392 tap-major ============
    // 8 warps: mg = wid&1 (M 32), ng = wid>>1 (N 32)
    {
        const int mg = wid & 1, ng = wid >> 1;
        const int mbase = mg * 32;
        const int ebase = ng * 32;
        const uint2* Wp = (const uint2*)(g_w1 + mg * (49 * 256));

        float d[2][4][4];
        #pragma unroll
        for (int mi = 0; mi < 2; ++mi)
            #pragma unroll
            for (int ni = 0; ni < 4; ++ni)
                #pragma unroll
                for (int r = 0; r < 4; ++r) d[mi][ni][r] = 0.f;

        uint2 P[2][4];
        #pragma unroll
        for (int s = 0; s < 2; ++s)
            #pragma unroll
            for (int j2 = 0; j2 < 4; ++j2)
                P[s][j2] = Wp[s * 128 + j2 * 32 + lane];

        #pragma unroll 1
        for (int ks = 0; ks < 49; ++ks) {
            const int sb = ks & 1;
            unsigned a0[4] = { P[sb][0].x, P[sb][0].y, P[sb][1].x, P[sb][1].y };
            unsigned a1[4] = { P[sb][2].x, P[sb][2].y, P[sb][3].x, P[sb][3].y };
            if (ks + 2 < 49) {
                #pragma unroll
                for (int j2 = 0; j2 < 4; ++j2)
                    P[sb][j2] = Wp[(ks + 2) * 128 + j2 * 32 + lane];
            }
            const int dk = ks / 7;
            const int ia = (ks % 7) * 8 + tg;
            const unsigned* B0 = SX + ia * SX_STRIDE + ebase + g + dk;
            const unsigned* B1 = B0 + 4 * SX_STRIDE;
            #pragma unroll
            for (int ni = 0; ni < 4; ++ni) {
                unsigned b[2] = { B0[ni * 8], B1[ni * 8] };
                mma_tf32(d[0][ni], a0, b);
                mma_tf32(d[1][ni], a1, b);
            }
        }
        // epilogue: bias + SiLU, store transposed tf32 into SH1[e][oa+3]
        #pragma unroll
        for (int mi = 0; mi < 2; ++mi)
            #pragma unroll
            for (int r2 = 0; r2 < 2; ++r2) {
                int oa = mbase + mi * 16 + g + r2 * 8;
                if (oa < 56) {
                    float bias = b_emb[oa];
                    #pragma unroll
                    for (int ni = 0; ni < 4; ++ni)
                        #pragma unroll
                        for (int c = 0; c < 2; ++c) {
                            int e = ebase + ni * 8 + tg * 2 + c;
                            float v = silu_f(d[mi][ni][r2 * 2 + c] + bias);
                            SH1[e * SH1_STRIDE + oa + 3] = f2tf(v);
                        }
                }
            }
    }
    __syncthreads();

    // ============ conv2: D[oe 128, a 64] = Watlas x im2col(h1T), K=896 tap-major ============
    // 8 warps: mg = wid&3 (M 32), nh = wid>>2 (N 32)
    {
        const int mg = wid & 3, nh = wid >> 2;
        const int mbase = mg * 32;
        const int abase = nh * 32;
        const uint2* Wp = (const uint2*)(g_w2 + mg * (112 * 256));

        float d[2][4][4];
        #pragma unroll
        for (int mi = 0; mi < 2; ++mi)
            #pragma unroll
            for (int ni = 0; ni < 4; ++ni)
                #pragma unroll
                for (int r = 0; r < 4; ++r) d[mi][ni][r] = 0.f;

        uint2 P[2][4];
        #pragma unroll
        for (int s = 0; s < 2; ++s)
            #pragma unroll
            for (int j2 = 0; j2 < 4; ++j2)
                P[s][j2] = Wp[s * 128 + j2 * 32 + lane];

        #pragma unroll 1
        for (int ks = 0; ks < 112; ++ks) {
            const int sb = ks & 1;
            unsigned a0[4] = { P[sb][0].x, P[sb][0].y, P[sb][1].x, P[sb][1].y };
            unsigned a1[4] = { P[sb][2].x, P[sb][2].y, P[sb][3].x, P[sb][3].y };
            if (ks + 2 < 112) {
                #pragma unroll
                for (int j2 = 0; j2 < 4; ++j2)
                    P[sb][j2] = Wp[(ks + 2) * 128 + j2 * 32 + lane];
            }
            const int dk = ks >> 4;
            const int ie = (ks & 15) * 8 + tg;
            const unsigned* B0 = SH1 + ie * SH1_STRIDE + abase + g + dk;
            const unsigned* B1 = B0 + 4 * SH1_STRIDE;
            #pragma unroll
            for (int ni = 0; ni < 4; ++ni) {
                unsigned b[2] = { B0[ni * 8], B1[ni * 8] };
                mma_tf32(d[0][ni], a0, b);
                mma_tf32(d[1][ni], a1, b);
            }
        }
        // epilogue: bias + SiLU + masked sum over a + quad reduce -> Sq[nh][oe]
        #pragma unroll
        for (int mi = 0; mi < 2; ++mi)
            #pragma unroll
            for (int r2 = 0; r2 < 2; ++r2) {
                int oe = mbase + mi * 16 + g + r2 * 8;
                float bias = b_atlas[oe];
                float s = 0.f;
                #pragma unroll
                for (int ni = 0; ni < 4; ++ni) {
                    if (nh * 4 + ni < 7) {   // a = abase+ni*8+... valid iff < 56
                        s += silu_f(d[mi][ni][r2 * 2 + 0] + bias);
                        s += silu_f(d[mi][ni][r2 * 2 + 1] + bias);
                    }
                }
                s += __shfl_xor_sync(0xffffffffu, s, 1);
                s += __shfl_xor_sync(0xffffffffu, s, 2);
                if (tg == 0) Sq[nh * 128 + oe] = s;
            }
    }
    __syncthreads();

    // ============ k-proj: D[o 128, l 64] = Wk x x^T, K=128 ============
    // 8 warps: mg = wid&3 (M 32), nh = wid>>2 (N 32)
    {
        const int mg = wid & 3, nh = wid >> 2;
        const int mbase = mg * 32;
        const int lbase = nh * 32;
        const uint2* Wp = (const uint2*)(g_w3 + mg * (16 * 256));

        float d[2][4][4];
        #pragma unroll
        for (int mi = 0; mi < 2; ++mi)
            #pragma unroll
            for (int ni = 0; ni < 4; ++ni)
                #pragma unroll
                for (int r = 0; r < 4; ++r) d[mi][ni][r] = 0.f;

        uint2 P[2][4];
        #pragma unroll
        for (int s = 0; s < 2; ++s)
            #pragma unroll
            for (int j2 = 0; j2 < 4; ++j2)
                P[s][j2] = Wp[s * 128 + j2 * 32 + lane];

        #pragma unroll 1
        for (int ks = 0; ks < 16; ++ks) {
            const int sb = ks & 1;
            unsigned a0[4] = { P[sb][0].x, P[sb][0].y, P[sb][1].x, P[sb][1].y };
            unsigned a1[4] = { P[sb][2].x, P[sb][2].y, P[sb][3].x, P[sb][3].y };
            if (ks + 2 < 16) {
                #pragma unroll
                for (int j2 = 0; j2 < 4; ++j2)
                    P[sb][j2] = Wp[(ks + 2) * 128 + j2 * 32 + lane];
            }
            const unsigned* Bp = SX + (lbase + g) * SX_STRIDE + 3 + ks * 8 + tg;
            #pragma unroll
            for (int ni = 0; ni < 4; ++ni) {
                unsigned b[2] = { Bp[ni * 8 * SX_STRIDE], Bp[ni * 8 * SX_STRIDE + 4] };
                mma_tf32(d[0][ni], a0, b);
                mma_tf32(d[1][ni], a1, b);
            }
        }
        // store K (SH1 region is free: conv2 reads completed before the sync above)
        #pragma unroll
        for (int mi = 0; mi < 2; ++mi)
            #pragma unroll
            for (int r2 = 0; r2 < 2; ++r2) {
                int o = mbase + mi * 16 + g + r2 * 8;
                #pragma unroll
                for (int ni = 0; ni < 4; ++ni)
                    #pragma unroll
                    for (int c = 0; c < 2; ++c) {
                        int l = lbase + ni * 8 + tg * 2 + c;
                        SK[l * SK_STRIDE + o] = d[mi][ni][r2 * 2 + c];
                    }
            }
    }
    __syncthreads();

    // ================ layernorms ================
    if (t < 8) {
        const int h = t;
        float qv[16];
        float m = 0.f;
        #pragma unroll
        for (int d = 0; d < 16; ++d) {
            qv[d] = (Sq[h * 16 + d] + Sq[128 + h * 16 + d]) * (1.0f / 56.0f);
            m += qv[d];
        }
        m *= (1.0f / 16.0f);
        float var = 0.f;
        #pragma unroll
        for (int d = 0; d < 16; ++d) { float dd = qv[d] - m; var += dd * dd; }
        var *= (1.0f / 16.0f);
        float rs = rsqrtf(var + LN_EPS);
        #pragma unroll
        for (int d = 0; d < 16; ++d)
            Sqn[h * 16 + d] = ((qv[d] - m) * rs * qn_w[d] + qn_b[d]) * SCALING;
    }
    for (int i = t; i < 448; i += 256) {
        const int l = i >> 3, h = i & 7;
        float* kp = SK + l * SK_STRIDE + h * 16;
        float m = 0.f;
        #pragma unroll
        for (int d = 0; d < 16; ++d) m += kp[d];
        m *= (1.0f / 16.0f);
        float var = 0.f;
        #pragma unroll
        for (int d = 0; d < 16; ++d) { float dd = kp[d] - m; var += dd * dd; }
        var *= (1.0f / 16.0f);
        float rs = rsqrtf(var + LN_EPS);
        #pragma unroll
        for (int d = 0; d < 16; ++d)
            kp[d] = (kp[d] - m) * rs * kn_w[d] + kn_b[d];
    }
    __syncthreads();

    // ================ attention + double softmax ================
    for (int i = t; i < 448; i += 256) {
        const int l = i >> 3, h = i & 7;
        const float* qp = Sqn + h * 16;
        const float* kp = SK + l * SK_STRIDE + h * 16;
        float s = 0.f;
        #pragma unroll
        for (int d = 0; d < 16; ++d) s += qp[d] * kp[d];
        SA[h * 60 + l] = s;
    }
    __syncthreads();
    if (t < 8) {
        float* row = SA + t * 60;
        float mx = -1e30f;
        for (int l = 0; l < 56; ++l) mx = fmaxf(mx, row[l]);
        float sum = 0.f;
        for (int l = 0; l < 56; ++l) { float e = __expf(row[l] - mx); row[l] = e; sum += e; }
        float inv = 1.0f / sum;
        for (int l = 0; l < 56; ++l) row[l] *= inv;
    }
    __syncthreads();
    if (t < 4) {
        const float lam = Ssc[0];
        const float* p0 = SA + (2 * t) * 60;
        const float* p1 = SA + (2 * t + 1) * 60;
        float* dst = SA2 + t * 60;
        float mx = -1e30f;
        for (int l = 0; l < 56; ++l) {
            float v = p0[l] - lam * p1[l];
            dst[l] = v;
            mx = fmaxf(mx, v);
        }
        float sum = 0.f;
        for (int l = 0; l < 56; ++l) { float e = __expf(dst[l] - mx); dst[l] = e; sum += e; }
        float inv = 1.0f / sum;
        for (int l = 0; l < 56; ++l) dst[l] *= inv;
    }
    __syncthreads();
    if (t < 56) {
        out[(size_t)blockIdx.x * 56 + t] =
            0.25f * (SA2[t] + SA2[60 + t] + SA2[120 + t] + SA2[180 + t]);
    }
}

extern "C" void kernel_launch(void* const* d_in, const int* in_sizes, int n_in,
                              void* d_out, int out_size) {
    const float* x       = (const float*)d_in[0];
    const float* w_emb   = (const float*)d_in[1];
    const float* b_emb   = (const float*)d_in[2];
    const float* w_atlas = (const float*)d_in[3];
    const float* b_atlas = (const float*)d_in[4];
    const float* w_k     = (const float*)d_in[5];
    const float* qn_w    = (const float*)d_in[6];
    const float* qn_b    = (const float*)d_in[7];
    const float* kn_w    = (const float*)d_in[8];
    const float* kn_b    = (const float*)d_in[9];
    const float* lq1     = (const float*)d_in[10];
    const float* lk1     = (const float*)d_in[11];
    const float* lq2     = (const float*)d_in[12];
    const float* lk2     = (const float*)d_in[13];
    float* out = (float*)d_out;

    const int B = in_sizes[0] / (A_DIM * E_DIM);

    repack_kernel<<<(W_TOTAL + 255) / 256, 256>>>(w_emb, w_atlas, w_k);

    const size_t smem = SMEM_WORDS * sizeof(unsigned);
    cudaFuncSetAttribute(atlas_mdattn_tc,
                         cudaFuncAttributeMaxDynamicSharedMemorySize, (int)smem);
    atlas_mdattn_tc<<<B, 256, smem>>>(
        x, b_emb, b_atlas,
        qn_w, qn_b, kn_w, kn_b, lq1, lk1, lq2, lk2, out);
}

// round 7
// speedup vs baseline: 1.6245x; 1.6245x over previous
#include <cuda_runtime.h>
#include <cuda_bf16.h>
#include <math.h>

// ---- problem constants ----
#define A_DIM 56
#define E_DIM 128
#define LAMBDA_INIT 0.7f
#define LN_EPS 1e-5f
#define SCALING 0.25f   // HD^-0.5, HD=16

// ---- repacked weight sizes (32-bit words, each = bf16x2) ----
#define K1_STEPS 28               // conv1: K padded 7*64=448, /16
#define K2_STEPS 56               // conv2: K = 7*128=896, /16
#define K3_STEPS 8                // kproj: K=128, /16
#define W1_WORDS (2 * K1_STEPS * 256)
#define W2_WORDS (4 * K2_STEPS * 256)
#define W3_WORDS (4 * K3_STEPS * 256)
#define W_TOTAL  (W1_WORDS + W2_WORDS + W3_WORDS)

__device__ __align__(16) unsigned g_w1[W1_WORDS];
__device__ __align__(16) unsigned g_w2[W2_WORDS];
__device__ __align__(16) unsigned g_w3[W3_WORDS];

// ---- smem layout (32-bit words), TWO batches per CTA ----
// SXE : [2][64][72]   bf16x2 pairs along e:  word(pe,l) = (x[l][2pe], x[l][2pe+1])
// SXB : [2][32][136]  bf16x2 pairs along ia: word(p, 3+e') = (x[2p][e'], x[2p+1][e'])  (ia 56..63 zero)
// SH1B: [2][64][72]   bf16x2 pairs along ie: word(pe,3+a') = (h1[a'][2pe], h1[a'][2pe+1])
// SK  : [2][64][132]  f32, overlays SXB+SH1B after conv2
#define SXE_B   4608
#define SXB_B   4352
#define SH1B_B  4608
#define SK_B    8448
#define SK_STRIDE 132

#define OFF_SXE   0
#define OFF_SXB   (OFF_SXE + 2 * SXE_B)            // 9216
#define OFF_SH1B  (OFF_SXB + 2 * SXB_B)            // 17920
#define OFF_SK    OFF_SXB                           // overlay (17920 words available >= 16896)
#define OFF_SQ    (OFF_SH1B + 2 * SH1B_B)          // 27136  [2][128]
#define OFF_SQN   (OFF_SQ + 256)                    // [2][128]
#define OFF_SA    (OFF_SQN + 256)                   // [2][8][60]
#define OFF_SA2   (OFF_SA + 960)                    // [2][4][60]
#define OFF_SC    (OFF_SA2 + 480)
#define SMEM_WORDS (OFF_SC + 4)                     // 29092 words = 116368 B

__device__ __forceinline__ float silu_f(float v) {
    return v / (1.0f + __expf(-v));
}
__device__ __forceinline__ unsigned pack_bf2(float lo, float hi) {
    unsigned u;
    asm("cvt.rn.bf16x2.f32 %0, %1, %2;" : "=r"(u) : "f"(hi), "f"(lo));
    return u;
}
__device__ __forceinline__ void mma_bf16(float* d, const unsigned* a, const unsigned* b) {
    asm volatile(
        "mma.sync.aligned.m16n8k16.row.col.f32.bf16.bf16.f32 "
        "{%0,%1,%2,%3}, {%4,%5,%6,%7}, {%8,%9}, {%0,%1,%2,%3};"
        : "+f"(d[0]), "+f"(d[1]), "+f"(d[2]), "+f"(d[3])
        : "r"(a[0]), "r"(a[1]), "r"(a[2]), "r"(a[3]), "r"(b[0]), "r"(b[1]));
}

// ================== weight repack: fragment-order bf16x2, TAP-MAJOR k ==================
// word idx per m-group block = ks*256 + j2*64 + lane*2 + p; j = 2*j2+p, mi = j>>2, r = j&3,
// row = mg*32 + mi*16 + g + (r&1)*8, hw-k base = 2*tg + (r>=2)*8, logical kk = ks*16 + hwk.
// conv1: kk = dk*64 + ia -> src col = ia*7 + dk (ia<56 else 0)
// conv2: kk = dk*128 + ie -> src col = ie*7 + dk
// kproj: col = kk
__global__ void __launch_bounds__(256)
repack_kernel(const float* __restrict__ w_emb,
              const float* __restrict__ w_atlas,
              const float* __restrict__ w_k)
{
    int i = blockIdx.x * 256 + threadIdx.x;
    if (i >= W_TOTAL) return;

    const float* src;
    unsigned* dst;
    int K, src_stride, row_lim, ii, which;
    if (i < W1_WORDS) {
        ii = i; src = w_emb; dst = g_w1; K = K1_STEPS; src_stride = 392; row_lim = 56; which = 1;
    } else if (i < W1_WORDS + W2_WORDS) {
        ii = i - W1_WORDS; src = w_atlas; dst = g_w2; K = K2_STEPS; src_stride = 896; row_lim = 128; which = 2;
    } else {
        ii = i - W1_WORDS - W2_WORDS; src = w_k; dst = g_w3; K = K3_STEPS; src_stride = 128; row_lim = 128; which = 3;
    }
    int p    = ii & 1;
    int lane = (ii >> 1) & 31;
    int j2   = (ii >> 6) & 3;
    int blk  = ii >> 8;
    int ks   = blk % K;
    int mg   = blk / K;
    int j    = j2 * 2 + p;
    int r    = j & 3;
    int g = lane >> 2, tg = lane & 3;
    int row = mg * 32 + (j >> 2) * 16 + g + ((r & 1) ? 8 : 0);
    int kk0 = ks * 16 + 2 * tg + ((r >= 2) ? 8 : 0);

    float v[2] = {0.f, 0.f};
    if (row < row_lim) {
        #pragma unroll
        for (int c = 0; c < 2; ++c) {
            int kk = kk0 + c;
            int col = -1;
            if (which == 1) {
                int dk = kk >> 6, ia = kk & 63;
                if (ia < 56) col = ia * 7 + dk;
            } else if (which == 2) {
                int dk = kk >> 7, ie = kk & 127;
                col = ie * 7 + dk;
            } else {
                col = kk;
            }
            if (col >= 0) v[c] = src[row * src_stride + col];
        }
    }
    dst[ii] = pack_bf2(v[0], v[1]);
}

extern __shared__ unsigned smw[];

__global__ void __launch_bounds__(256, 1)
atlas_mdattn_tc(
    const float* __restrict__ x,       // [B,56,128]
    const float* __restrict__ b_emb,   // [56]
    const float* __restrict__ b_atlas, // [128]
    const float* __restrict__ qn_w, const float* __restrict__ qn_b,
    const float* __restrict__ kn_w, const float* __restrict__ kn_b,
    const float* __restrict__ lq1, const float* __restrict__ lk1,
    const float* __restrict__ lq2, const float* __restrict__ lk2,
    float* __restrict__ out)           // [B,56]
{
    const int t = threadIdx.x;
    const int lane = t & 31, wid = t >> 5;
    const int g = lane >> 2, tg = lane & 3;

    char* smb = (char*)smw;
    unsigned* SXE  = smw + OFF_SXE;
    unsigned* SXB  = smw + OFF_SXB;
    unsigned* SH1B = smw + OFF_SH1B;
    float* SK  = (float*)(smw + OFF_SK);
    float* Sq  = (float*)(smw + OFF_SQ);
    float* Sqn = (float*)(smw + OFF_SQN);
    float* SA  = (float*)(smw + OFF_SA);
    float* SA2 = (float*)(smw + OFF_SA2);
    float* Ssc = (float*)(smw + OFF_SC);

    // ---------------- init ----------------
    {
        uint4 z = make_uint4(0, 0, 0, 0);
        uint4* p = (uint4*)smw;
        for (int i = t; i < OFF_SQ / 4; i += 256) p[i] = z;
    }
    if (t == 0) {
        float s1 = 0.f, s2 = 0.f;
        #pragma unroll
        for (int d = 0; d < 16; ++d) { s1 += lq1[d] * lk1[d]; s2 += lq2[d] * lk2[d]; }
        Ssc[0] = __expf(s1) - __expf(s2) + LAMBDA_INIT;
    }
    __syncthreads();

    // load x (2 batches), bf16, into BOTH pair layouts
    const float* xb = x + (size_t)blockIdx.x * 2 * (A_DIM * E_DIM);
    #pragma unroll
    for (int bb = 0; bb < 2; ++bb) {
        for (int i = t; i < A_DIM * E_DIM; i += 256) {
            int l = i >> 7, e = i & 127;
            __nv_bfloat16 hv = __float2bfloat16(xb[bb * A_DIM * E_DIM + i]);
            // SXB: pairs along ia(l): word (l>>1, 3+e), half l&1
            *(__nv_bfloat16*)(smb + (((OFF_SXB + bb * SXB_B) + (l >> 1) * 136 + 3 + e) << 2) + ((l & 1) << 1)) = hv;
            // SXE: pairs along e: word (e>>1, l), half e&1
            *(__nv_bfloat16*)(smb + (((OFF_SXE + bb * SXE_B) + (e >> 1) * 72 + l) << 2) + ((e & 1) << 1)) = hv;
        }
    }
    __syncthreads();

    // ============ conv1: D[oa 64, (b,e) 256] = Wemb x im2col(x), K=448(pad) ============
    {
        const int mg = wid & 1, ng = wid >> 1;
        const int mbase = mg * 32;
        const int batch = ng >> 1;
        const int ebase = (ng & 1) * 64;
        const unsigned* SXBb = SXB + batch * SXB_B;
        const uint2* Wp = (const uint2*)(g_w1 + mg * (K1_STEPS * 256));

        float d[2][8][4];
        #pragma unroll
        for (int mi = 0; mi < 2; ++mi)
            #pragma unroll
            for (int ni = 0; ni < 8; ++ni)
                #pragma unroll
                for (int r = 0; r < 4; ++r) d[mi][ni][r] = 0.f;

        uint2 P[2][4];
        #pragma unroll
        for (int s = 0; s < 2; ++s)
            #pragma unroll
            for (int j2 = 0; j2 < 4; ++j2)
                P[s][j2] = Wp[s * 128 + j2 * 32 + lane];

        #pragma unroll 1
        for (int ks = 0; ks < K1_STEPS; ++ks) {
            const int sb = ks & 1;
            unsigned a0[4] = { P[sb][0].x, P[sb][0].y, P[sb][1].x, P[sb][1].y };
            unsigned a1[4] = { P[sb][2].x, P[sb][2].y, P[sb][3].x, P[sb][3].y };
            if (ks + 2 < K1_STEPS) {
                #pragma unroll
                for (int j2 = 0; j2 < 4; ++j2)
                    P[sb][j2] = Wp[(ks + 2) * 128 + j2 * 32 + lane];
            }
            const int dk = ks >> 2;              // tap
            const int p0 = (ks & 3) * 8 + tg;    // ia pair for reg0
            const unsigned* B0 = SXBb + p0 * 136 + ebase + g + dk;
            const unsigned* B1 = B0 + 4 * 136;   // reg1 pair = p0+4
            #pragma unroll
            for (int ni = 0; ni < 8; ++ni) {
                unsigned b[2] = { B0[ni * 8], B1[ni * 8] };
                mma_bf16(d[0][ni], a0, b);
                mma_bf16(d[1][ni], a1, b);
            }
        }
        // epilogue: bias + SiLU, write h1 (channel ie=e, position a'=oa) into SH1B pair layout
        #pragma unroll
        for (int mi = 0; mi < 2; ++mi)
            #pragma unroll
            for (int r2 = 0; r2 < 2; ++r2) {
                int oa = mbase + mi * 16 + g + r2 * 8;
                if (oa < 56) {
                    float bias = b_emb[oa];
                    #pragma unroll
                    for (int ni = 0; ni < 8; ++ni)
                        #pragma unroll
                        for (int c = 0; c < 2; ++c) {
                            int e = ebase + ni * 8 + tg * 2 + c;
                            float v = silu_f(d[mi][ni][r2 * 2 + c] + bias);
                            *(__nv_bfloat16*)(smb +
                                (((OFF_SH1B + batch * SH1B_B) + (e >> 1) * 72 + 3 + oa) << 2) + ((e & 1) << 1))
                                = __float2bfloat16(v);
                        }
                }
            }
    }
    __syncthreads();

    // ============ conv2: D[oe 128, (b,a) 128] = Watlas x im2col(h1T), K=896 ============
    {
        const int mg = wid & 3, batch = wid >> 2;
        const int mbase = mg * 32;
        const unsigned* SHb = SH1B + batch * SH1B_B;
        const uint2* Wp = (const uint2*)(g_w2 + mg * (K2_STEPS * 256));

        float d[2][8][4];
        #pragma unroll
        for (int mi = 0; mi < 2; ++mi)
            #pragma unroll
            for (int ni = 0; ni < 8; ++ni)
                #pragma unroll
                for (int r = 0; r < 4; ++r) d[mi][ni][r] = 0.f;

        uint2 P[2][4];
        #pragma unroll
        for (int s = 0; s < 2; ++s)
            #pragma unroll
            for (int j2 = 0; j2 < 4; ++j2)
                P[s][j2] = Wp[s * 128 + j2 * 32 + lane];

        #pragma unroll 1
        for (int ks = 0; ks < K2_STEPS; ++ks) {
            const int sb = ks & 1;
            unsigned a0[4] = { P[sb][0].x, P[sb][0].y, P[sb][1].x, P[sb][1].y };
            unsigned a1[4] = { P[sb][2].x, P[sb][2].y, P[sb][3].x, P[sb][3].y };
            if (ks + 2 < K2_STEPS) {
                #pragma unroll
                for (int j2 = 0; j2 < 4; ++j2)
                    P[sb][j2] = Wp[(ks + 2) * 128 + j2 * 32 + lane];
            }
            const int dk = ks >> 3;              // tap
            const int p0 = (ks & 7) * 8 + tg;    // ie pair for reg0
            const unsigned* B0 = SHb + p0 * 72 + g + dk;
            const unsigned* B1 = B0 + 4 * 72;
            #pragma unroll
            for (int ni = 0; ni < 8; ++ni) {
                unsigned b[2] = { B0[ni * 8], B1[ni * 8] };
                mma_bf16(d[0][ni], a0, b);
                mma_bf16(d[1][ni], a1, b);
            }
        }
        // epilogue: bias + SiLU + masked sum over a + quad reduce -> Sq[batch][oe]
        #pragma unroll
        for (int mi = 0; mi < 2; ++mi)
            #pragma unroll
            for (int r2 = 0; r2 < 2; ++r2) {
                int oe = mbase + mi * 16 + g + r2 * 8;
                float bias = b_atlas[oe];
                float s = 0.f;
                #pragma unroll
                for (int ni = 0; ni < 8; ++ni)
                    #pragma unroll
                    for (int c = 0; c < 2; ++c) {
                        int a = ni * 8 + tg * 2 + c;
                        if (a < 56) s += silu_f(d[mi][ni][r2 * 2 + c] + bias);
                    }
                s += __shfl_xor_sync(0xffffffffu, s, 1);
                s += __shfl_xor_sync(0xffffffffu, s, 2);
                if (tg == 0) Sq[batch * 128 + oe] = s;
            }
    }
    __syncthreads();

    // ============ k-proj: D[o 128, (b,l) 128] = Wk x x^T, K=128 ============
    {
        const int mg = wid & 3, batch = wid >> 2;
        const int mbase = mg * 32;
        const unsigned* SXEb = SXE + batch * SXE_B;
        const uint2* Wp = (const uint2*)(g_w3 + mg * (K3_STEPS * 256));

        float d[2][8][4];
        #pragma unroll
        for (int mi = 0; mi < 2; ++mi)
            #pragma unroll
            for (int ni = 0; ni < 8; ++ni)
                #pragma unroll
                for (int r = 0; r < 4; ++r) d[mi][ni][r] = 0.f;

        uint2 P[2][4];
        #pragma unroll
        for (int s = 0; s < 2; ++s)
            #pragma unroll
            for (int j2 = 0; j2 < 4; ++j2)
                P[s][j2] = Wp[s * 128 + j2 * 32 + lane];

        #pragma unroll 1
        for (int ks = 0; ks < K3_STEPS; ++ks) {
            const int sb = ks & 1;
            unsigned a0[4] = { P[sb][0].x, P[sb][0].y, P[sb][1].x, P[sb][1].y };
            unsigned a1[4] = { P[sb][2].x, P[sb][2].y, P[sb][3].x, P[sb][3].y };
            if (ks + 2 < K3_STEPS) {
                #pragma unroll
                for (int j2 = 0; j2 < 4; ++j2)
                    P[sb][j2] = Wp[(ks + 2) * 128 + j2 * 32 + lane];
            }
            const int p0 = ks * 8 + tg;          // e pair for reg0
            const unsigned* B0 = SXEb + p0 * 72 + g;
            const unsigned* B1 = B0 + 4 * 72;
            #pragma unroll
            for (int ni = 0; ni < 8; ++ni) {
                unsigned b[2] = { B0[ni * 8], B1[ni * 8] };
                mma_bf16(d[0][ni], a0, b);
                mma_bf16(d[1][ni], a1, b);
            }
        }
        // store K as f32 (SK overlays SXB+SH1B, both dead after the sync above)
        #pragma unroll
        for (int mi = 0; mi < 2; ++mi)
            #pragma unroll
            for (int r2 = 0; r2 < 2; ++r2) {
                int o = mbase + mi * 16 + g + r2 * 8;
                #pragma unroll
                for (int ni = 0; ni < 8; ++ni)
                    #pragma unroll
                    for (int c = 0; c < 2; ++c) {
                        int l = ni * 8 + tg * 2 + c;
                        SK[batch * SK_B + l * SK_STRIDE + o] = d[mi][ni][r2 * 2 + c];
                    }
            }
    }
    __syncthreads();

    // ================ layernorms ================
    if (t < 16) {
        const int batch = t >> 3, h = t & 7;
        float qv[16];
        float m = 0.f;
        #pragma unroll
        for (int d = 0; d < 16; ++d) {
            qv[d] = Sq[batch * 128 + h * 16 + d] * (1.0f / 56.0f);
            m += qv[d];
        }
        m *= (1.0f / 16.0f);
        float var = 0.f;
        #pragma unroll
        for (int d = 0; d < 16; ++d) { float dd = qv[d] - m; var += dd * dd; }
        var *= (1.0f / 16.0f);
        float rs = rsqrtf(var + LN_EPS);
        #pragma unroll
        for (int d = 0; d < 16; ++d)
            Sqn[batch * 128 + h * 16 + d] = ((qv[d] - m) * rs * qn_w[d] + qn_b[d]) * SCALING;
    }
    for (int i = t; i < 896; i += 256) {
        const int batch = (i >= 448) ? 1 : 0;
        const int g2 = i - batch * 448;
        const int l = g2 >> 3, h = g2 & 7;
        float* kp = SK + batch * SK_B + l * SK_STRIDE + h * 16;
        float m = 0.f;
        #pragma unroll
        for (int d = 0; d < 16; ++d) m += kp[d];
        m *= (1.0f / 16.0f);
        float var = 0.f;
        #pragma unroll
        for (int d = 0; d < 16; ++d) { float dd = kp[d] - m; var += dd * dd; }
        var *= (1.0f / 16.0f);
        float rs = rsqrtf(var + LN_EPS);
        #pragma unroll
        for (int d = 0; d < 16; ++d)
            kp[d] = (kp[d] - m) * rs * kn_w[d] + kn_b[d];
    }
    __syncthreads();

    // ================ attention + double softmax ================
    for (int i = t; i < 896; i += 256) {
        const int batch = (i >= 448) ? 1 : 0;
        const int g2 = i - batch * 448;
        const int l = g2 >> 3, h = g2 & 7;
        const float* qp = Sqn + batch * 128 + h * 16;
        const float* kp = SK + batch * SK_B + l * SK_STRIDE + h * 16;
        float s = 0.f;
        #pragma unroll
        for (int d = 0; d < 16; ++d) s += qp[d] * kp[d];
        SA[batch * 480 + h * 60 + l] = s;
    }
    __syncthreads();
    if (t < 16) {
        const int batch = t >> 3, h = t & 7;
        float* row = SA + batch * 480 + h * 60;
        float mx = -1e30f;
        for (int l = 0; l < 56; ++l) mx = fmaxf(mx, row[l]);
        float sum = 0.f;
        for (int l = 0; l < 56; ++l) { float e = __expf(row[l] - mx); row[l] = e; sum += e; }
        float inv = 1.0f / sum;
        for (int l = 0; l < 56; ++l) row[l] *= inv;
    }
    __syncthreads();
    if (t < 8) {
        const int batch = t >> 2, hh = t & 3;
        const float lam = Ssc[0];
        const float* p0 = SA + batch * 480 + (2 * hh) * 60;
        const float* p1 = SA + batch * 480 + (2 * hh + 1) * 60;
        float* dst = SA2 + batch * 240 + hh * 60;
        float mx = -1e30f;
        for (int l = 0; l < 56; ++l) {
            float v = p0[l] - lam * p1[l];
            dst[l] = v;
            mx = fmaxf(mx, v);
        }
        float sum = 0.f;
        for (int l = 0; l < 56; ++l) { float e = __expf(dst[l] - mx); dst[l] = e; sum += e; }
        float inv = 1.0f / sum;
        for (int l = 0; l < 56; ++l) dst[l] *= inv;
    }
    __syncthreads();
    if (t < 112) {
        const int batch = (t >= 56) ? 1 : 0;
        const int l = t - batch * 56;
        const float* base = SA2 + batch * 240;
        out[((size_t)blockIdx.x * 2 + batch) * 56 + l] =
            0.25f * (base[l] + base[60 + l] + base[120 + l] + base[180 + l]);
    }
}

extern "C" void kernel_launch(void* const* d_in, const int* in_sizes, int n_in,
                              void* d_out, int out_size) {
    const float* x       = (const float*)d_in[0];
    const float* w_emb   = (const float*)d_in[1];
    const float* b_emb   = (const float*)d_in[2];
    const float* w_atlas = (const float*)d_in[3];
    const float* b_atlas = (const float*)d_in[4];
    const float* w_k     = (const float*)d_in[5];
    const float* qn_w    = (const float*)d_in[6];
    const float* qn_b    = (const float*)d_in[7];
    const float* kn_w    = (const float*)d_in[8];
    const float* kn_b    = (const float*)d_in[9];
    const float* lq1     = (const float*)d_in[10];
    const float* lk1     = (const float*)d_in[11];
    const float* lq2     = (const float*)d_in[12];
    const float* lk2     = (const float*)d_in[13];
    float* out = (float*)d_out;

    const int B = in_sizes[0] / (A_DIM * E_DIM);

    repack_kernel<<<(W_TOTAL + 255) / 256, 256>>>(w_emb, w_atlas, w_k);

    const size_t smem = SMEM_WORDS * sizeof(unsigned);
    cudaFuncSetAttribute(atlas_mdattn_tc,
                         cudaFuncAttributeMaxDynamicSharedMemorySize, (int)smem);
    atlas_mdattn_tc<<<B / 2, 256, smem>>>(
        x, b_emb, b_atlas,
        qn_w, qn_b, kn_w, kn_b, lq1, lk1, lq2, lk2, out);
}

// round 8
// speedup vs baseline: 2.2637x; 1.3935x over previous
#include <cuda_runtime.h>
#include <cuda_bf16.h>
#include <math.h>

// ---- problem constants ----
#define A_DIM 56
#define E_DIM 128
#define LAMBDA_INIT 0.7f
#define LN_EPS 1e-5f
#define SCALING 0.25f   // HD^-0.5, HD=16

// ---- repacked weight sizes (32-bit words, each = bf16x2) ----
#define K1_STEPS 28               // conv1: K padded 7*64=448, /16
#define K2_STEPS 56               // conv2: K = 7*128=896, /16
#define K3_STEPS 8                // kproj: K=128, /16
#define W1_WORDS (2 * K1_STEPS * 256)
#define W2_WORDS (4 * K2_STEPS * 256)
#define W3_WORDS (4 * K3_STEPS * 256)
#define W_TOTAL  (W1_WORDS + W2_WORDS + W3_WORDS)

__device__ __align__(16) unsigned g_w1[W1_WORDS];
__device__ __align__(16) unsigned g_w2[W2_WORDS];
__device__ __align__(16) unsigned g_w3[W3_WORDS];

// ---- smem layout (32-bit words), TWO batches per CTA, 2 CTAs/SM ----
// SXB : [2][32][136]  bf16x2 pairs along ia: word(p, 3+e') = (x[2p][e'], x[2p+1][e'])  (ia 56..63 zero)
// SH1B: [2][64][72]   bf16x2 pairs along ie: word(pe,3+a') = (h1[a'][2pe], h1[a'][2pe+1])
// SK  : [2][64][132]  f32, overlays SXB+SH1B after conv2 (kproj B comes from global)
#define SXB_B   4352
#define SH1B_B  4608
#define SK_B    8448
#define SK_STRIDE 132

#define OFF_SXB   0
#define OFF_SH1B  (OFF_SXB + 2 * SXB_B)            // 8704
#define OFF_SK    0                                 // overlay (17920 words >= 16896)
#define OFF_SQ    (OFF_SH1B + 2 * SH1B_B)          // 17920  [2][128]
#define OFF_SQN   (OFF_SQ + 256)                    // [2][128]
#define OFF_SA    (OFF_SQN + 256)                   // [2][8][60]
#define OFF_SA2   (OFF_SA + 960)                    // [2][4][60]
#define OFF_SC    (OFF_SA2 + 480)
#define SMEM_WORDS (OFF_SC + 4)                     // 19876 words = 79504 B -> 2 CTAs/SM

__device__ __forceinline__ float silu_f(float v) {
    return v / (1.0f + __expf(-v));
}
__device__ __forceinline__ unsigned pack_bf2(float lo, float hi) {
    unsigned u;
    asm("cvt.rn.bf16x2.f32 %0, %1, %2;" : "=r"(u) : "f"(hi), "f"(lo));
    return u;
}
__device__ __forceinline__ void mma_bf16(float* d, const unsigned* a, const unsigned* b) {
    asm volatile(
        "mma.sync.aligned.m16n8k16.row.col.f32.bf16.bf16.f32 "
        "{%0,%1,%2,%3}, {%4,%5,%6,%7}, {%8,%9}, {%0,%1,%2,%3};"
        : "+f"(d[0]), "+f"(d[1]), "+f"(d[2]), "+f"(d[3])
        : "r"(a[0]), "r"(a[1]), "r"(a[2]), "r"(a[3]), "r"(b[0]), "r"(b[1]));
}

// ================== weight repack: fragment-order bf16x2, TAP-MAJOR k ==================
// word idx per m-group block = ks*256 + j2*64 + lane*2 + p; j = 2*j2+p, mi = j>>2, r = j&3,
// row = mg*32 + mi*16 + g + (r&1)*8, hw-k base = 2*tg + (r>=2)*8, logical kk = ks*16 + hwk.
// conv1: kk = dk*64 + ia -> src col = ia*7 + dk (ia<56 else 0)
// conv2: kk = dk*128 + ie -> src col = ie*7 + dk
// kproj: col = kk
__global__ void __launch_bounds__(256)
repack_kernel(const float* __restrict__ w_emb,
              const float* __restrict__ w_atlas,
              const float* __restrict__ w_k)
{
    int i = blockIdx.x * 256 + threadIdx.x;
    if (i >= W_TOTAL) return;

    const float* src;
    unsigned* dst;
    int K, src_stride, row_lim, ii, which;
    if (i < W1_WORDS) {
        ii = i; src = w_emb; dst = g_w1; K = K1_STEPS; src_stride = 392; row_lim = 56; which = 1;
    } else if (i < W1_WORDS + W2_WORDS) {
        ii = i - W1_WORDS; src = w_atlas; dst = g_w2; K = K2_STEPS; src_stride = 896; row_lim = 128; which = 2;
    } else {
        ii = i - W1_WORDS - W2_WORDS; src = w_k; dst = g_w3; K = K3_STEPS; src_stride = 128; row_lim = 128; which = 3;
    }
    int p    = ii & 1;
    int lane = (ii >> 1) & 31;
    int j2   = (ii >> 6) & 3;
    int blk  = ii >> 8;
    int ks   = blk % K;
    int mg   = blk / K;
    int j    = j2 * 2 + p;
    int r    = j & 3;
    int g = lane >> 2, tg = lane & 3;
    int row = mg * 32 + (j >> 2) * 16 + g + ((r & 1) ? 8 : 0);
    int kk0 = ks * 16 + 2 * tg + ((r >= 2) ? 8 : 0);

    float v[2] = {0.f, 0.f};
    if (row < row_lim) {
        #pragma unroll
        for (int c = 0; c < 2; ++c) {
            int kk = kk0 + c;
            int col = -1;
            if (which == 1) {
                int dk = kk >> 6, ia = kk & 63;
                if (ia < 56) col = ia * 7 + dk;
            } else if (which == 2) {
                int dk = kk >> 7, ie = kk & 127;
                col = ie * 7 + dk;
            } else {
                col = kk;
            }
            if (col >= 0) v[c] = src[row * src_stride + col];
        }
    }
    dst[ii] = pack_bf2(v[0], v[1]);
}

extern __shared__ unsigned smw[];

__global__ void __launch_bounds__(256, 2)
atlas_mdattn_tc(
    const float* __restrict__ x,       // [B,56,128]
    const float* __restrict__ b_emb,   // [56]
    const float* __restrict__ b_atlas, // [128]
    const float* __restrict__ qn_w, const float* __restrict__ qn_b,
    const float* __restrict__ kn_w, const float* __restrict__ kn_b,
    const float* __restrict__ lq1, const float* __restrict__ lk1,
    const float* __restrict__ lq2, const float* __restrict__ lk2,
    float* __restrict__ out)           // [B,56]
{
    const int t = threadIdx.x;
    const int lane = t & 31, wid = t >> 5;
    const int g = lane >> 2, tg = lane & 3;

    char* smb = (char*)smw;
    unsigned* SXB  = smw + OFF_SXB;
    unsigned* SH1B = smw + OFF_SH1B;
    float* SK  = (float*)(smw + OFF_SK);
    float* Sq  = (float*)(smw + OFF_SQ);
    float* Sqn = (float*)(smw + OFF_SQN);
    float* SA  = (float*)(smw + OFF_SA);
    float* SA2 = (float*)(smw + OFF_SA2);
    float* Ssc = (float*)(smw + OFF_SC);

    // ---------------- init ----------------
    {
        uint4 z = make_uint4(0, 0, 0, 0);
        uint4* p = (uint4*)smw;
        for (int i = t; i < OFF_SQ / 4; i += 256) p[i] = z;
    }
    if (t == 0) {
        float s1 = 0.f, s2 = 0.f;
        #pragma unroll
        for (int d = 0; d < 16; ++d) { s1 += lq1[d] * lk1[d]; s2 += lq2[d] * lk2[d]; }
        Ssc[0] = __expf(s1) - __expf(s2) + LAMBDA_INIT;
    }
    __syncthreads();

    // load x (2 batches), bf16, into ia-pair layout (for conv1)
    const float* xb = x + (size_t)blockIdx.x * 2 * (A_DIM * E_DIM);
    #pragma unroll
    for (int bb = 0; bb < 2; ++bb) {
        for (int i = t; i < A_DIM * E_DIM; i += 256) {
            int l = i >> 7, e = i & 127;
            __nv_bfloat16 hv = __float2bfloat16(xb[bb * A_DIM * E_DIM + i]);
            *(__nv_bfloat16*)(smb + (((OFF_SXB + bb * SXB_B) + (l >> 1) * 136 + 3 + e) << 2) + ((l & 1) << 1)) = hv;
        }
    }
    __syncthreads();

    // ============ conv1: D[oa 64, (b,e) 256] = Wemb x im2col(x), K=448(pad) ============
    {
        const int mg = wid & 1, ng = wid >> 1;
        const int mbase = mg * 32;
        const int batch = ng >> 1;
        const int ebase = (ng & 1) * 64;
        const unsigned* SXBb = SXB + batch * SXB_B;
        const uint2* Wp = (const uint2*)(g_w1 + mg * (K1_STEPS * 256));

        float d[2][8][4];
        #pragma unroll
        for (int mi = 0; mi < 2; ++mi)
            #pragma unroll
            for (int ni = 0; ni < 8; ++ni)
                #pragma unroll
                for (int r = 0; r < 4; ++r) d[mi][ni][r] = 0.f;

        uint2 P[2][4];
        #pragma unroll
        for (int s = 0; s < 2; ++s)
            #pragma unroll
            for (int j2 = 0; j2 < 4; ++j2)
                P[s][j2] = Wp[s * 128 + j2 * 32 + lane];

        #pragma unroll 1
        for (int ks = 0; ks < K1_STEPS; ++ks) {
            const int sb = ks & 1;
            unsigned a0[4] = { P[sb][0].x, P[sb][0].y, P[sb][1].x, P[sb][1].y };
            unsigned a1[4] = { P[sb][2].x, P[sb][2].y, P[sb][3].x, P[sb][3].y };
            if (ks + 2 < K1_STEPS) {
                #pragma unroll
                for (int j2 = 0; j2 < 4; ++j2)
                    P[sb][j2] = Wp[(ks + 2) * 128 + j2 * 32 + lane];
            }
            const int dk = ks >> 2;              // tap
            const int p0 = (ks & 3) * 8 + tg;    // ia pair for reg0
            const unsigned* B0 = SXBb + p0 * 136 + ebase + g + dk;
            const unsigned* B1 = B0 + 4 * 136;   // reg1 pair = p0+4
            #pragma unroll
            for (int ni = 0; ni < 8; ++ni) {
                unsigned b[2] = { B0[ni * 8], B1[ni * 8] };
                mma_bf16(d[0][ni], a0, b);
                mma_bf16(d[1][ni], a1, b);
            }
        }
        // epilogue: bias + SiLU, write h1 (channel ie=e, position a'=oa) into SH1B pair layout
        #pragma unroll
        for (int mi = 0; mi < 2; ++mi)
            #pragma unroll
            for (int r2 = 0; r2 < 2; ++r2) {
                int oa = mbase + mi * 16 + g + r2 * 8;
                if (oa < 56) {
                    float bias = b_emb[oa];
                    #pragma unroll
                    for (int ni = 0; ni < 8; ++ni)
                        #pragma unroll
                        for (int c = 0; c < 2; ++c) {
                            int e = ebase + ni * 8 + tg * 2 + c;
                            float v = silu_f(d[mi][ni][r2 * 2 + c] + bias);
                            *(__nv_bfloat16*)(smb +
                                (((OFF_SH1B + batch * SH1B_B) + (e >> 1) * 72 + 3 + oa) << 2) + ((e & 1) << 1))
                                = __float2bfloat16(v);
                        }
                }
            }
    }
    __syncthreads();

    // ============ conv2: D[oe 128, (b,a) 128] = Watlas x im2col(h1T), K=896 ============
    {
        const int mg = wid & 3, batch = wid >> 2;
        const int mbase = mg * 32;
        const unsigned* SHb = SH1B + batch * SH1B_B;
        const uint2* Wp = (const uint2*)(g_w2 + mg * (K2_STEPS * 256));

        float d[2][8][4];
        #pragma unroll
        for (int mi = 0; mi < 2; ++mi)
            #pragma unroll
            for (int ni = 0; ni < 8; ++ni)
                #pragma unroll
                for (int r = 0; r < 4; ++r) d[mi][ni][r] = 0.f;

        uint2 P[2][4];
        #pragma unroll
        for (int s = 0; s < 2; ++s)
            #pragma unroll
            for (int j2 = 0; j2 < 4; ++j2)
                P[s][j2] = Wp[s * 128 + j2 * 32 + lane];

        #pragma unroll 1
        for (int ks = 0; ks < K2_STEPS; ++ks) {
            const int sb = ks & 1;
            unsigned a0[4] = { P[sb][0].x, P[sb][0].y, P[sb][1].x, P[sb][1].y };
            unsigned a1[4] = { P[sb][2].x, P[sb][2].y, P[sb][3].x, P[sb][3].y };
            if (ks + 2 < K2_STEPS) {
                #pragma unroll
                for (int j2 = 0; j2 < 4; ++j2)
                    P[sb][j2] = Wp[(ks + 2) * 128 + j2 * 32 + lane];
            }
            const int dk = ks >> 3;              // tap
            const int p0 = (ks & 7) * 8 + tg;    // ie pair for reg0
            const unsigned* B0 = SHb + p0 * 72 + g + dk;
            const unsigned* B1 = B0 + 4 * 72;
            #pragma unroll
            for (int ni = 0; ni < 8; ++ni) {
                unsigned b[2] = { B0[ni * 8], B1[ni * 8] };
                mma_bf16(d[0][ni], a0, b);
                mma_bf16(d[1][ni], a1, b);
            }
        }
        // epilogue: bias + SiLU + masked sum over a + quad reduce -> Sq[batch][oe]
        #pragma unroll
        for (int mi = 0; mi < 2; ++mi)
            #pragma unroll
            for (int r2 = 0; r2 < 2; ++r2) {
                int oe = mbase + mi * 16 + g + r2 * 8;
                float bias = b_atlas[oe];
                float s = 0.f;
                #pragma unroll
                for (int ni = 0; ni < 8; ++ni)
                    #pragma unroll
                    for (int c = 0; c < 2; ++c) {
                        int a = ni * 8 + tg * 2 + c;
                        if (a < 56) s += silu_f(d[mi][ni][r2 * 2 + c] + bias);
                    }
                s += __shfl_xor_sync(0xffffffffu, s, 1);
                s += __shfl_xor_sync(0xffffffffu, s, 2);
                if (tg == 0) Sq[batch * 128 + oe] = s;
            }
    }
    __syncthreads();

    // ============ k-proj: D[o 128, (b,l) 128] = Wk x x^T, K=128 (B from GLOBAL) ============
    {
        const int mg = wid & 3, batch = wid >> 2;
        const int mbase = mg * 32;
        const float2* xp = (const float2*)(xb + batch * (A_DIM * E_DIM));
        const uint2* Wp = (const uint2*)(g_w3 + mg * (K3_STEPS * 256));

        float d[2][8][4];
        #pragma unroll
        for (int mi = 0; mi < 2; ++mi)
            #pragma unroll
            for (int ni = 0; ni < 8; ++ni)
                #pragma unroll
                for (int r = 0; r < 4; ++r) d[mi][ni][r] = 0.f;

        uint2 P[2][4];
        #pragma unroll
        for (int s = 0; s < 2; ++s)
            #pragma unroll
            for (int j2 = 0; j2 < 4; ++j2)
                P[s][j2] = Wp[s * 128 + j2 * 32 + lane];

        #pragma unroll 1
        for (int ks = 0; ks < K3_STEPS; ++ks) {
            const int sb = ks & 1;
            unsigned a0[4] = { P[sb][0].x, P[sb][0].y, P[sb][1].x, P[sb][1].y };
            unsigned a1[4] = { P[sb][2].x, P[sb][2].y, P[sb][3].x, P[sb][3].y };
            if (ks + 2 < K3_STEPS) {
                #pragma unroll
                for (int j2 = 0; j2 < 4; ++j2)
                    P[sb][j2] = Wp[(ks + 2) * 128 + j2 * 32 + lane];
            }
            const int p0 = ks * 8 + tg;          // e-pair index for reg0 (reg1 = p0+4)
            #pragma unroll
            for (int ni = 0; ni < 8; ++ni) {
                const int l = ni * 8 + g;
                unsigned b[2];
                if (l < 56) {
                    float2 v0 = xp[l * 64 + p0];
                    float2 v1 = xp[l * 64 + p0 + 4];
                    b[0] = pack_bf2(v0.x, v0.y);
                    b[1] = pack_bf2(v1.x, v1.y);
                } else {
                    b[0] = 0u; b[1] = 0u;
                }
                mma_bf16(d[0][ni], a0, b);
                mma_bf16(d[1][ni], a1, b);
            }
        }
        __syncthreads();   // SXB/SH1B reads done in all warps; SK overlay now safe
        #pragma unroll
        for (int mi = 0; mi < 2; ++mi)
            #pragma unroll
            for (int r2 = 0; r2 < 2; ++r2) {
                int o = mbase + mi * 16 + g + r2 * 8;
                #pragma unroll
                for (int ni = 0; ni < 8; ++ni)
                    #pragma unroll
                    for (int c = 0; c < 2; ++c) {
                        int l = ni * 8 + tg * 2 + c;
                        SK[batch * SK_B + l * SK_STRIDE + o] = d[mi][ni][r2 * 2 + c];
                    }
            }
    }
    __syncthreads();

    // ================ layernorms ================
    if (t < 16) {
        const int batch = t >> 3, h = t & 7;
        float qv[16];
        float m = 0.f;
        #pragma unroll
        for (int d = 0; d < 16; ++d) {
            qv[d] = Sq[batch * 128 + h * 16 + d] * (1.0f / 56.0f);
            m += qv[d];
        }
        m *= (1.0f / 16.0f);
        float var = 0.f;
        #pragma unroll
        for (int d = 0; d < 16; ++d) { float dd = qv[d] - m; var += dd * dd; }
        var *= (1.0f / 16.0f);
        float rs = rsqrtf(var + LN_EPS);
        #pragma unroll
        for (int d = 0; d < 16; ++d)
            Sqn[batch * 128 + h * 16 + d] = ((qv[d] - m) * rs * qn_w[d] + qn_b[d]) * SCALING;
    }
    for (int i = t; i < 896; i += 256) {
        const int batch = (i >= 448) ? 1 : 0;
        const int g2 = i - batch * 448;
        const int l = g2 >> 3, h = g2 & 7;
        float* kp = SK + batch * SK_B + l * SK_STRIDE + h * 16;
        float m = 0.f;
        #pragma unroll
        for (int d = 0; d < 16; ++d) m += kp[d];
        m *= (1.0f / 16.0f);
        float var = 0.f;
        #pragma unroll
        for (int d = 0; d < 16; ++d) { float dd = kp[d] - m; var += dd * dd; }
        var *= (1.0f / 16.0f);
        float rs = rsqrtf(var + LN_EPS);
        #pragma unroll
        for (int d = 0; d < 16; ++d)
            kp[d] = (kp[d] - m) * rs * kn_w[d] + kn_b[d];
    }
    __syncthreads();

    // ================ attention + double softmax ================
    for (int i = t; i < 896; i += 256) {
        const int batch = (i >= 448) ? 1 : 0;
        const int g2 = i - batch * 448;
        const int l = g2 >> 3, h = g2 & 7;
        const float* qp = Sqn + batch * 128 + h * 16;
        const float* kp = SK + batch * SK_B + l * SK_STRIDE + h * 16;
        float s = 0.f;
        #pragma unroll
        for (int d = 0; d < 16; ++d) s += qp[d] * kp[d];
        SA[batch * 480 + h * 60 + l] = s;
    }
    __syncthreads();
    if (t < 16) {
        const int batch = t >> 3, h = t & 7;
        float* row = SA + batch * 480 + h * 60;
        float mx = -1e30f;
        for (int l = 0; l < 56; ++l) mx = fmaxf(mx, row[l]);
        float sum = 0.f;
        for (int l = 0; l < 56; ++l) { float e = __expf(row[l] - mx); row[l] = e; sum += e; }
        float inv = 1.0f / sum;
        for (int l = 0; l < 56; ++l) row[l] *= inv;
    }
    __syncthreads();
    if (t < 8) {
        const int batch = t >> 2, hh = t & 3;
        const float lam = Ssc[0];
        const float* p0 = SA + batch * 480 + (2 * hh) * 60;
        const float* p1 = SA + batch * 480 + (2 * hh + 1) * 60;
        float* dst = SA2 + batch * 240 + hh * 60;
        float mx = -1e30f;
        for (int l = 0; l < 56; ++l) {
            float v = p0[l] - lam * p1[l];
            dst[l] = v;
            mx = fmaxf(mx, v);
        }
        float sum = 0.f;
        for (int l = 0; l < 56; ++l) { float e = __expf(dst[l] - mx); dst[l] = e; sum += e; }
        float inv = 1.0f / sum;
        for (int l = 0; l < 56; ++l) dst[l] *= inv;
    }
    __syncthreads();
    if (t < 112) {
        const int batch = (t >= 56) ? 1 : 0;
        const int l = t - batch * 56;
        const float* base = SA2 + batch * 240;
        out[((size_t)blockIdx.x * 2 + batch) * 56 + l] =
            0.25f * (base[l] + base[60 + l] + base[120 + l] + base[180 + l]);
    }
}

extern "C" void kernel_launch(void* const* d_in, const int* in_sizes, int n_in,
                              void* d_out, int out_size) {
    const float* x       = (const float*)d_in[0];
    const float* w_emb   = (const float*)d_in[1];
    const float* b_emb   = (const float*)d_in[2];
    const float* w_atlas = (const float*)d_in[3];
    const float* b_atlas = (const float*)d_in[4];
    const float* w_k     = (const float*)d_in[5];
    const float* qn_w    = (const float*)d_in[6];
    const float* qn_b    = (const float*)d_in[7];
    const float* kn_w    = (const float*)d_in[8];
    const float* kn_b    = (const float*)d_in[9];
    const float* lq1     = (const float*)d_in[10];
    const float* lk1     = (const float*)d_in[11];
    const float* lq2     = (const float*)d_in[12];
    const float* lk2     = (const float*)d_in[13];
    float* out = (float*)d_out;

    const int B = in_sizes[0] / (A_DIM * E_DIM);

    repack_kernel<<<(W_TOTAL + 255) / 256, 256>>>(w_emb, w_atlas, w_k);

    const size_t smem = SMEM_WORDS * sizeof(unsigned);
    cudaFuncSetAttribute(atlas_mdattn_tc,
                         cudaFuncAttributeMaxDynamicSharedMemorySize, (int)smem);
    atlas_mdattn_tc<<<B / 2, 256, smem>>>(
        x, b_emb, b_atlas,
        qn_w, qn_b, kn_w, kn_b, lq1, lk1, lq2, lk2, out);
}